// round 15
// baseline (speedup 1.0000x reference)
#include <cuda_runtime.h>
#include <cuda_bf16.h>
#include <math.h>

#define NN 16384
#define FF 256
#define HH 128
#define CC 40
#define KTOP 32
#define DEG 16
#define EE (NN*DEG)            // 262144
#define NK (NN*KTOP)           // 524288
#define ETOT (EE + 2*NK)       // 1310720

// output layout (float32 flatten of the tuple) — confirmed by out_size=7733248
#define OFF_OUT 0
#define SZ_OUT (NN*CC)
#define OFF_MIDIDX (SZ_OUT)
#define OFF_MIDV (OFF_MIDIDX + 4*NK)
#define OFF_NEWIDX (OFF_MIDV + 2*NK)
#define OFF_NEWV (OFF_NEWIDX + 2*ETOT)

#define OSTORE(ofs, val) do { long long _o = (long long)(ofs); \
    if (_o >= 0 && _o < osz) out[_o] = (val); } while (0)

// ---------------- device scratch ----------------
// RULE: these symbols are referenced ONLY inside device code (host-passed
// shadow addresses silently resolve to host RAM via GB300 ATS).
__device__ int   g_mode;   // confirmed 0 = int32
__device__ int   g_lay;    // confirmed 0 = [2,E] planar
__device__ float g_is0[NN];
__device__ float g_nvals0[EE];
__device__ float g_emb1[NN*FF];
__device__ float g_emb[NN*FF];
__device__ float g_embT[NN*FF];
__device__ float g_topv[NK];
__device__ int   g_topi[NK];
__device__ int   g_hist[NN];
__device__ float g_degsum[NN];
__device__ float g_isnew[NN];
__device__ int   g_rowptr[NN+1];
__device__ int   g_cursor[NN];
__device__ int   g_csr_col[ETOT];
__device__ float g_csr_val[ETOT];
__device__ float g_xw1[NN*HH];
__device__ float g_h[NN*HH];
__device__ float g_hw2[NN*CC];

__device__ __forceinline__ long long dec(const void* p, long long i, int m) {
    if (m == 0) return (long long)((const int*)p)[i];
    if (m == 1) return ((const long long*)p)[i];
    if (m == 2) return (long long)((const float*)p)[i];
    return (long long)((const double*)p)[i];
}
__device__ __forceinline__ long long rpos(long long e, int lay) { return lay ? 2*e     : e; }
__device__ __forceinline__ long long cpos(long long e, int lay) { return lay ? 2*e + 1 : (long long)EE + e; }
__device__ __forceinline__ long long row_raw(const void* p, long long e) { return dec(p, rpos(e, g_lay), g_mode); }
__device__ __forceinline__ long long col_raw(const void* p, long long e) { return dec(p, cpos(e, g_lay), g_mode); }
__device__ __forceinline__ int col_of(const void* p, long long e) {
    long long v = col_raw(p, e);
    if (v < 0) v = 0;
    if (v >= NN) v = NN - 1;
    return (int)v;
}

// XLA f32 tanh, FMA-CONTRACTED polynomial (aarch64 LLVM fast-math contracts
// the elemental mul+add chains into fma).
__device__ __forceinline__ float xla_tanh(float x) {
    float ax = fabsf(x);
    if (ax < 0.0004f) return x;
    float xc = fminf(fmaxf(x, -7.90531110763549805f), 7.90531110763549805f);
    float x2 = __fmul_rn(xc, xc);
    float p = -2.76076847742355e-16f;
    p = __fmaf_rn(x2, p,  2.00018790482477e-13f);
    p = __fmaf_rn(x2, p, -8.60467152213735e-11f);
    p = __fmaf_rn(x2, p,  5.12229709037114e-08f);
    p = __fmaf_rn(x2, p,  1.48572235717979e-05f);
    p = __fmaf_rn(x2, p,  6.37261928875436e-04f);
    p = __fmaf_rn(x2, p,  4.89352455891786e-03f);
    p = __fmul_rn(xc, p);
    float q =  1.19825839466702e-06f;
    q = __fmaf_rn(x2, q, 1.18534705686654e-04f);
    q = __fmaf_rn(x2, q, 2.26843463243900e-03f);
    q = __fmaf_rn(x2, q, 4.89352518554385e-03f);
    return __fdiv_rn(p, q);
}

// exhaustive (dtype x layout) detector; verified mode=0 lay=0 on this dataset
__global__ void k_detect8(const void* idx) {
    __shared__ int rs[8], cs[8];
    int t = threadIdx.x;
    if (t < 8) { rs[t] = 0; cs[t] = 0; }
    __syncthreads();
    for (int c = 0; c < 8; c++) {
        int m = c & 3, lay = c >> 2;
        int good = 0;
        for (int s = t; s < 2048; s += 256) {
            long long e = (long long)s * 63 + 5;
            good += (dec(idx, rpos(e, lay), m) == (e >> 4));
        }
        atomicAdd(&rs[c], good);
    }
    __syncthreads();
    for (int c = 0; c < 8; c++) {
        if (rs[c] != 2048) continue;
        int m = c & 3, lay = c >> 2;
        int good = 0;
        for (int s = t; s < 2048; s += 256) {
            long long e = (long long)s * (EE/2048) + 13;
            long long v = dec(idx, cpos(e, lay), m);
            good += (v > 0 && v < NN);
        }
        atomicAdd(&cs[c], good);
    }
    __syncthreads();
    if (t == 0) {
        int best = 0, bs = -1;
        for (int c = 0; c < 8; c++) {
            int sc = rs[c] * 4 + cs[c];
            if (sc > bs) { bs = sc; best = c; }
        }
        g_mode = best & 3;
        g_lay  = best >> 2;
    }
}

// ---------------- graph0 ----------------
__global__ void k_deg0(const float* __restrict__ vals) {
    int r = blockIdx.x * blockDim.x + threadIdx.x;
    if (r >= NN) return;
    float s = 0.f;
#pragma unroll
    for (int j = 0; j < DEG; j++) s = __fadd_rn(s, vals[r*DEG + j]);
    float t = __fadd_rn(__fsqrt_rn(s), 1e-10f);
    g_is0[r] = __fdiv_rn(1.f, t);
}

__global__ void k_nvals0(const void* __restrict__ idx, const float* __restrict__ vals) {
    int e = blockIdx.x * blockDim.x + threadIdx.x;
    if (e >= EE) return;
    int c = col_of(idx, e);
    g_nvals0[e] = __fmul_rn(__fmul_rn(vals[e], g_is0[e >> 4]), g_is0[c]);
}

// gather SpMM on fixed-degree-16 graph; edge-sequential rounded mul/add to
// match XLA segment_sum (scatter-add). PASS 0: x -> tanh -> g_emb1.
// PASS 1: g_emb1 -> g_emb. (Wd1/Wd2 == 1.0 exactly: multiply is exact.)
template<int PASS>
__global__ void k_spmm16(const float* __restrict__ xin, const float* __restrict__ W,
                         const void* __restrict__ idx) {
    const float* in = (PASS == 0) ? xin : g_emb1;
    float* outp     = (PASS == 0) ? g_emb1 : g_emb;
    int r = blockIdx.x;
    int f = threadIdx.x;
    __shared__ int   sc[DEG];
    __shared__ float sv[DEG];
    if (f < DEG) {
        sc[f] = col_of(idx, (long long)r*DEG + f);
        sv[f] = g_nvals0[r*DEG + f];
    }
    __syncthreads();
    float w = W[f];
    float acc = 0.f;
#pragma unroll
    for (int j = 0; j < DEG; j++) {
        float xv = __fmul_rn(in[sc[j]*FF + f], w);     // x*Wd (elementwise, first)
        acc = __fadd_rn(acc, __fmul_rn(sv[j], xv));    // scatter-add semantics
    }
    outp[r*FF + f] = (PASS == 0) ? xla_tanh(acc) : acc;
}

// row L2 normalize: LLVM fast-math vectorized reduce on aarch64 NEON:
// 16 strided lane accumulators (4-wide x interleave 4), FMA-contracted squares,
// pairwise register tree (A0+A1)+(A2+A3), then 4-lane shuffle-halving.
__global__ void k_rownorm_vec() {
    int r = blockIdx.x * blockDim.x + threadIdx.x;
    if (r >= NN) return;
    float* row = &g_emb[r*FF];
    float a[16];
#pragma unroll
    for (int l = 0; l < 16; l++) a[l] = 0.f;
#pragma unroll 2
    for (int m = 0; m < 16; m++)
#pragma unroll
        for (int l = 0; l < 16; l++) {
            float v = row[m*16 + l];
            a[l] = __fmaf_rn(v, v, a[l]);
        }
    float c[4];
#pragma unroll
    for (int j = 0; j < 4; j++)
        c[j] = __fadd_rn(__fadd_rn(a[j], a[j+4]), __fadd_rn(a[j+8], a[j+12]));
    float d0 = __fadd_rn(c[0], c[2]);
    float d1 = __fadd_rn(c[1], c[3]);
    float s  = __fadd_rn(d0, d1);
    float nrm = fmaxf(__fsqrt_rn(s), 1e-12f);
#pragma unroll 8
    for (int f = 0; f < FF; f++) row[f] = __fdiv_rn(row[f], nrm);
}

__global__ void k_transpose() {
    __shared__ float t[32][33];
    int bn = blockIdx.x * 32, bf = blockIdx.y * 32;
    t[threadIdx.y][threadIdx.x] = g_emb[(bn + threadIdx.y)*FF + bf + threadIdx.x];
    __syncthreads();
    g_embT[(bf + threadIdx.y)*NN + bn + threadIdx.x] = t[threadIdx.x][threadIdx.y];
}

// ---------------- sim = half1@half1.T + half2@half2.T, fused top-32 ----------------
// Replicates XLA/Eigen dot: per-element SEQUENTIAL FMA over k within each half,
// halves combined with one rounded add.
__global__ __launch_bounds__(256) void k_simtopk2() {
    __shared__ float srow[16][256];
    __shared__ float tile[16][257];
    __shared__ float lv[16][KTOP];
    __shared__ int   li[16][KTOP];
    const int tid = threadIdx.x;
    const int r0 = blockIdx.x * 16;

    for (int i = tid; i < 16*256; i += 256)
        srow[i >> 8][i & 255] = g_emb[(r0 + (i >> 8))*FF + (i & 255)];
    for (int i = tid; i < 16*KTOP; i += 256) {
        lv[i >> 5][i & 31] = -3.4e38f;
        li[i >> 5][i & 31] = 0;
    }
    __syncthreads();

    for (int chunk = 0; chunk < 64; chunk++) {
        const int c = chunk*256 + tid;
        float a1[16], a2[16];
#pragma unroll
        for (int r = 0; r < 16; r++) { a1[r] = 0.f; a2[r] = 0.f; }
#pragma unroll 4
        for (int f = 0; f < 128; f++) {
            float b = g_embT[f*NN + c];
#pragma unroll
            for (int r = 0; r < 16; r++) a1[r] = __fmaf_rn(srow[r][f], b, a1[r]);
        }
#pragma unroll 4
        for (int f = 128; f < 256; f++) {
            float b = g_embT[f*NN + c];
#pragma unroll
            for (int r = 0; r < 16; r++) a2[r] = __fmaf_rn(srow[r][f], b, a2[r]);
        }
#pragma unroll
        for (int r = 0; r < 16; r++) tile[r][tid] = __fadd_rn(a1[r], a2[r]);
        __syncthreads();

        if (tid < 16) {
            float* L  = lv[tid];
            int*   LI = li[tid];
            float vm = L[KTOP-1];
#pragma unroll 1
            for (int cc = 0; cc < 256; cc++) {
                float v = tile[tid][cc];
                if (v > vm) {
                    int k = KTOP-1;
                    while (k > 0 && L[k-1] < v) {
                        L[k] = L[k-1];
                        LI[k] = LI[k-1];
                        --k;
                    }
                    L[k] = v;
                    LI[k] = chunk*256 + cc;
                    vm = L[KTOP-1];
                }
            }
        }
        __syncthreads();
    }

    for (int i = tid; i < 16*KTOP; i += 256) {
        int r = i >> 5, k = i & 31;
        g_topv[(r0 + r)*KTOP + k] = lv[r][k];
        g_topi[(r0 + r)*KTOP + k] = li[r][k];
    }
}

// ---------------- output writers ----------------
__global__ void k_write_fixed(const void* __restrict__ idx, const float* __restrict__ vals,
                              float* __restrict__ out, long long osz) {
    int e = blockIdx.x * blockDim.x + threadIdx.x;
    if (e >= EE) return;
    OSTORE(OFF_NEWIDX + e,        (float)row_raw(idx, e));
    OSTORE(OFF_NEWIDX + ETOT + e, (float)col_raw(idx, e));
    OSTORE(OFF_NEWV + e,          vals[e]);
}

__global__ void k_write_topk(float* __restrict__ out, long long osz) {
    int i = blockIdx.x * blockDim.x + threadIdx.x;
    if (i >= NK) return;
    int row = i >> 5;
    float fr = (float)row;
    float fc = (float)g_topi[i];
    float v  = g_topv[i];
    OSTORE(OFF_MIDIDX + i,          fr);
    OSTORE(OFF_MIDIDX + NK + i,     fc);
    OSTORE(OFF_MIDIDX + 2*NK + i,   fc);
    OSTORE(OFF_MIDIDX + 3*NK + i,   fr);
    OSTORE(OFF_MIDV + i,            v);
    OSTORE(OFF_MIDV + NK + i,       v);
    OSTORE(OFF_NEWIDX + EE + i,             fr);
    OSTORE(OFF_NEWIDX + EE + NK + i,        fc);
    OSTORE(OFF_NEWIDX + ETOT + EE + i,      fc);
    OSTORE(OFF_NEWIDX + ETOT + EE + NK + i, fr);
    OSTORE(OFF_NEWV + EE + i,       v);
    OSTORE(OFF_NEWV + EE + NK + i,  v);
}

// ---------------- new graph: degrees + CSR ----------------
__global__ void k_zero() {
    int r = blockIdx.x * blockDim.x + threadIdx.x;
    if (r >= NN) return;
    g_hist[r] = 0;
    g_degsum[r] = 0.f;
}

__global__ void k_hist(const float* __restrict__ vals) {
    int e = blockIdx.x * blockDim.x + threadIdx.x;
    if (e >= ETOT) return;
    int row; float val;
    if (e < EE)           { row = e >> 4;                         val = vals[e]; }
    else if (e < EE + NK) { int i = e - EE;      row = i >> 5;    val = g_topv[i]; }
    else                  { int i = e - EE - NK; row = g_topi[i]; val = g_topv[i]; }
    atomicAdd(&g_hist[row], 1);
    atomicAdd(&g_degsum[row], val);
}

__global__ void k_isnew() {
    int r = blockIdx.x * blockDim.x + threadIdx.x;
    if (r >= NN) return;
    float t = __fadd_rn(__fsqrt_rn(g_degsum[r]), 1e-10f);
    g_isnew[r] = __fdiv_rn(1.f, t);
}

__global__ void k_rowptr() {
    __shared__ int tsum[256];
    __shared__ int tpre[256];
    int t = threadIdx.x;
    int s = 0;
    for (int j = 0; j < 64; j++) s += g_hist[t*64 + j];
    tsum[t] = s;
    __syncthreads();
    if (t == 0) {
        int run = 0;
        for (int i = 0; i < 256; i++) { tpre[i] = run; run += tsum[i]; }
    }
    __syncthreads();
    int run = tpre[t];
    for (int j = 0; j < 64; j++) {
        int r = t*64 + j;
        g_rowptr[r] = run;
        g_cursor[r] = run;
        run += g_hist[r];
    }
    if (t == 255) g_rowptr[NN] = run;
}

__global__ void k_scatter(const void* __restrict__ idx, const float* __restrict__ vals) {
    int e = blockIdx.x * blockDim.x + threadIdx.x;
    if (e >= ETOT) return;
    int row, col; float val;
    if (e < EE) {
        row = e >> 4;
        col = col_of(idx, e);
        val = vals[e];
    } else if (e < EE + NK) {
        int i = e - EE;
        row = i >> 5;
        col = g_topi[i];
        val = g_topv[i];
    } else {
        int i = e - EE - NK;
        row = g_topi[i];
        col = i >> 5;
        val = g_topv[i];
    }
    int p = atomicAdd(&g_cursor[row], 1);
    g_csr_col[p] = col;
    g_csr_val[p] = __fmul_rn(__fmul_rn(val, g_isnew[row]), g_isnew[col]);
}

// ---------------- dense GEMM; scratch operands resolved in device code ----------------
template<int WHICH>
__global__ __launch_bounds__(256) void k_dgemm(const float* __restrict__ Aarg,
                                               const float* __restrict__ B) {
    constexpr int Ka = WHICH ? HH : FF;
    constexpr int Nc = WHICH ? CC : HH;
    const float* A = WHICH ? g_h : Aarg;
    float* C       = WHICH ? g_hw2 : g_xw1;
    __shared__ float As[16][64];
    __shared__ float Bs[16][64];
    int tid = threadIdx.x;
    int rb = blockIdx.x * 64, cb = blockIdx.y * 64;
    int tx = tid & 15, ty = tid >> 4;
    float acc[4][4];
#pragma unroll
    for (int i = 0; i < 4; i++)
#pragma unroll
        for (int j = 0; j < 4; j++) acc[i][j] = 0.f;

    int ar = tid >> 2, ac4 = (tid & 3) * 4;
    int bk = tid >> 4, bc = (tid & 15) * 4;
    for (int kk = 0; kk < Ka; kk += 16) {
        float4 a4 = *(const float4*)&A[(rb + ar)*Ka + kk + ac4];
        float4 b4;
        int bcg = cb + bc;
        if (bcg + 3 < Nc) {
            b4 = *(const float4*)&B[(kk + bk)*Nc + bcg];
        } else {
            b4.x = (bcg + 0 < Nc) ? B[(kk + bk)*Nc + bcg + 0] : 0.f;
            b4.y = (bcg + 1 < Nc) ? B[(kk + bk)*Nc + bcg + 1] : 0.f;
            b4.z = (bcg + 2 < Nc) ? B[(kk + bk)*Nc + bcg + 2] : 0.f;
            b4.w = (bcg + 3 < Nc) ? B[(kk + bk)*Nc + bcg + 3] : 0.f;
        }
        __syncthreads();
        As[ac4+0][ar] = a4.x; As[ac4+1][ar] = a4.y; As[ac4+2][ar] = a4.z; As[ac4+3][ar] = a4.w;
        Bs[bk][bc+0] = b4.x; Bs[bk][bc+1] = b4.y; Bs[bk][bc+2] = b4.z; Bs[bk][bc+3] = b4.w;
        __syncthreads();
#pragma unroll
        for (int k = 0; k < 16; k++) {
            float a[4], b[4];
#pragma unroll
            for (int i = 0; i < 4; i++) a[i] = As[k][ty*4 + i];
#pragma unroll
            for (int j = 0; j < 4; j++) b[j] = Bs[k][tx*4 + j];
#pragma unroll
            for (int i = 0; i < 4; i++)
#pragma unroll
                for (int j = 0; j < 4; j++) acc[i][j] += a[i] * b[j];
        }
    }
#pragma unroll
    for (int i = 0; i < 4; i++)
#pragma unroll
        for (int j = 0; j < 4; j++) {
            int cc = cb + tx*4 + j;
            if (cc < Nc) C[(rb + ty*4 + i)*Nc + cc] = acc[i][j];
        }
}

// CSR gather SpMM layer 1: g_h = relu(spmm(new, g_xw1) + bg1)
__global__ void k_spmm_csr_h(const float* __restrict__ bias) {
    int r = blockIdx.x;
    int f = threadIdx.x;
    int p0 = g_rowptr[r], p1 = g_rowptr[r+1];
    float acc = 0.f;
    for (int p = p0; p < p1; p++) acc += g_csr_val[p] * g_xw1[g_csr_col[p]*HH + f];
    acc += bias[f];
    g_h[r*HH + f] = fmaxf(acc, 0.f);
}

// CSR gather SpMM layer 2 (logits): out = spmm(new, g_hw2) + bg2
__global__ void k_spmm_csr_out(const float* __restrict__ bias,
                               float* __restrict__ out, long long osz) {
    int r = blockIdx.x;
    int f = threadIdx.x;
    int p0 = g_rowptr[r], p1 = g_rowptr[r+1];
    float acc = 0.f;
    for (int p = p0; p < p1; p++) acc += g_csr_val[p] * g_hw2[g_csr_col[p]*CC + f];
    acc += bias[f];
    OSTORE((long long)r*CC + f, acc);
}

// ---------------- launch ----------------
extern "C" void kernel_launch(void* const* d_in, const int* in_sizes, int n_in,
                              void* d_out, int out_size) {
    const float* x       = (const float*)d_in[0];
    const void*  adj_idx = d_in[1];
    const float* adj_val = (const float*)d_in[2];
    const float* Wd1     = (const float*)d_in[3];
    const float* Wd2     = (const float*)d_in[4];
    const float* Wg1     = (const float*)d_in[5];
    const float* bg1     = (const float*)d_in[6];
    const float* Wg2     = (const float*)d_in[7];
    const float* bg2     = (const float*)d_in[8];
    float* out = (float*)d_out;
    const long long osz = (long long)out_size;

    k_detect8<<<1, 256>>>(adj_idx);

    k_deg0<<<NN/256, 256>>>(adj_val);
    k_nvals0<<<EE/256, 256>>>(adj_idx, adj_val);
    k_spmm16<0><<<NN, FF>>>(x, Wd1, adj_idx);
    k_spmm16<1><<<NN, FF>>>(x, Wd2, adj_idx);
    k_rownorm_vec<<<NN/256, 256>>>();

    k_transpose<<<dim3(NN/32, FF/32), dim3(32, 32)>>>();
    k_simtopk2<<<NN/16, 256>>>();

    k_write_fixed<<<EE/256, 256>>>(adj_idx, adj_val, out, osz);
    k_write_topk<<<NK/256, 256>>>(out, osz);

    k_zero<<<NN/256, 256>>>();
    k_hist<<<ETOT/256, 256>>>(adj_val);
    k_isnew<<<NN/256, 256>>>();
    k_rowptr<<<1, 256>>>();
    k_scatter<<<ETOT/256, 256>>>(adj_idx, adj_val);

    // task GCN (commuted dense layers: spmm(A,x)@W == spmm(A, x@W))
    k_dgemm<0><<<dim3(NN/64, HH/64), 256>>>(x, Wg1);
    k_spmm_csr_h<<<NN, HH>>>(bg1);
    k_dgemm<1><<<dim3(NN/64, 1), 256>>>(x, Wg2);
    k_spmm_csr_out<<<NN, CC>>>(bg2, out, osz);
}

// round 16
// speedup vs baseline: 2.7447x; 2.7447x over previous
#include <cuda_runtime.h>
#include <cuda_bf16.h>
#include <math.h>

#define NN 16384
#define FF 256
#define HH 128
#define CC 40
#define KTOP 32
#define DEG 16
#define EE (NN*DEG)            // 262144
#define NK (NN*KTOP)           // 524288
#define ETOT (EE + 2*NK)       // 1310720

// output layout (float32 flatten of the tuple) — confirmed by out_size=7733248
#define OFF_OUT 0
#define SZ_OUT (NN*CC)
#define OFF_MIDIDX (SZ_OUT)
#define OFF_MIDV (OFF_MIDIDX + 4*NK)
#define OFF_NEWIDX (OFF_MIDV + 2*NK)
#define OFF_NEWV (OFF_NEWIDX + 2*ETOT)

#define OSTORE(ofs, val) do { long long _o = (long long)(ofs); \
    if (_o >= 0 && _o < osz) out[_o] = (val); } while (0)

// ---------------- device scratch ----------------
// RULE: these symbols are referenced ONLY inside device code (host-passed
// shadow addresses silently resolve to host RAM via GB300 ATS).
__device__ int   g_mode;   // confirmed 0 = int32
__device__ int   g_lay;    // confirmed 0 = [2,E] planar
__device__ float g_is0[NN];
__device__ float g_nvals0[EE];
__device__ float g_emb1[NN*FF];
__device__ float g_emb[NN*FF];
__device__ float g_topv[NK];
__device__ int   g_topi[NK];
__device__ int   g_hist[NN];
__device__ float g_degsum[NN];
__device__ float g_isnew[NN];
__device__ int   g_rowptr[NN+1];
__device__ int   g_cursor[NN];
__device__ int   g_csr_col[ETOT];
__device__ float g_csr_val[ETOT];
__device__ float g_xw1[NN*HH];
__device__ float g_h[NN*HH];
__device__ float g_hw2[NN*CC];

__device__ __forceinline__ long long dec(const void* p, long long i, int m) {
    if (m == 0) return (long long)((const int*)p)[i];
    if (m == 1) return ((const long long*)p)[i];
    if (m == 2) return (long long)((const float*)p)[i];
    return (long long)((const double*)p)[i];
}
__device__ __forceinline__ long long rpos(long long e, int lay) { return lay ? 2*e     : e; }
__device__ __forceinline__ long long cpos(long long e, int lay) { return lay ? 2*e + 1 : (long long)EE + e; }
__device__ __forceinline__ long long row_raw(const void* p, long long e) { return dec(p, rpos(e, g_lay), g_mode); }
__device__ __forceinline__ long long col_raw(const void* p, long long e) { return dec(p, cpos(e, g_lay), g_mode); }
__device__ __forceinline__ int col_of(const void* p, long long e) {
    long long v = col_raw(p, e);
    if (v < 0) v = 0;
    if (v >= NN) v = NN - 1;
    return (int)v;
}

// XLA f32 tanh, FMA-contracted polynomial (verified: closes tie-break gap).
__device__ __forceinline__ float xla_tanh(float x) {
    float ax = fabsf(x);
    if (ax < 0.0004f) return x;
    float xc = fminf(fmaxf(x, -7.90531110763549805f), 7.90531110763549805f);
    float x2 = __fmul_rn(xc, xc);
    float p = -2.76076847742355e-16f;
    p = __fmaf_rn(x2, p,  2.00018790482477e-13f);
    p = __fmaf_rn(x2, p, -8.60467152213735e-11f);
    p = __fmaf_rn(x2, p,  5.12229709037114e-08f);
    p = __fmaf_rn(x2, p,  1.48572235717979e-05f);
    p = __fmaf_rn(x2, p,  6.37261928875436e-04f);
    p = __fmaf_rn(x2, p,  4.89352455891786e-03f);
    p = __fmul_rn(xc, p);
    float q =  1.19825839466702e-06f;
    q = __fmaf_rn(x2, q, 1.18534705686654e-04f);
    q = __fmaf_rn(x2, q, 2.26843463243900e-03f);
    q = __fmaf_rn(x2, q, 4.89352518554385e-03f);
    return __fdiv_rn(p, q);
}

// exhaustive (dtype x layout) detector; verified mode=0 lay=0 on this dataset
__global__ void k_detect8(const void* idx) {
    __shared__ int rs[8], cs[8];
    int t = threadIdx.x;
    if (t < 8) { rs[t] = 0; cs[t] = 0; }
    __syncthreads();
    for (int c = 0; c < 8; c++) {
        int m = c & 3, lay = c >> 2;
        int good = 0;
        for (int s = t; s < 2048; s += 256) {
            long long e = (long long)s * 63 + 5;
            good += (dec(idx, rpos(e, lay), m) == (e >> 4));
        }
        atomicAdd(&rs[c], good);
    }
    __syncthreads();
    for (int c = 0; c < 8; c++) {
        if (rs[c] != 2048) continue;
        int m = c & 3, lay = c >> 2;
        int good = 0;
        for (int s = t; s < 2048; s += 256) {
            long long e = (long long)s * (EE/2048) + 13;
            long long v = dec(idx, cpos(e, lay), m);
            good += (v > 0 && v < NN);
        }
        atomicAdd(&cs[c], good);
    }
    __syncthreads();
    if (t == 0) {
        int best = 0, bs = -1;
        for (int c = 0; c < 8; c++) {
            int sc = rs[c] * 4 + cs[c];
            if (sc > bs) { bs = sc; best = c; }
        }
        g_mode = best & 3;
        g_lay  = best >> 2;
    }
}

// ---------------- graph0 ----------------
__global__ void k_deg0(const float* __restrict__ vals) {
    int r = blockIdx.x * blockDim.x + threadIdx.x;
    if (r >= NN) return;
    float s = 0.f;
#pragma unroll
    for (int j = 0; j < DEG; j++) s = __fadd_rn(s, vals[r*DEG + j]);
    float t = __fadd_rn(__fsqrt_rn(s), 1e-10f);
    g_is0[r] = __fdiv_rn(1.f, t);
}

__global__ void k_nvals0(const void* __restrict__ idx, const float* __restrict__ vals) {
    int e = blockIdx.x * blockDim.x + threadIdx.x;
    if (e >= EE) return;
    int c = col_of(idx, e);
    g_nvals0[e] = __fmul_rn(__fmul_rn(vals[e], g_is0[e >> 4]), g_is0[c]);
}

// gather SpMM on fixed-degree-16 graph; edge-sequential rounded mul/add
// (XLA segment_sum semantics). PASS 0: x -> tanh -> g_emb1. PASS 1: -> g_emb.
template<int PASS>
__global__ void k_spmm16(const float* __restrict__ xin, const float* __restrict__ W,
                         const void* __restrict__ idx) {
    const float* in = (PASS == 0) ? xin : g_emb1;
    float* outp     = (PASS == 0) ? g_emb1 : g_emb;
    int r = blockIdx.x;
    int f = threadIdx.x;
    __shared__ int   sc[DEG];
    __shared__ float sv[DEG];
    if (f < DEG) {
        sc[f] = col_of(idx, (long long)r*DEG + f);
        sv[f] = g_nvals0[r*DEG + f];
    }
    __syncthreads();
    float w = W[f];
    float acc = 0.f;
#pragma unroll
    for (int j = 0; j < DEG; j++) {
        float xv = __fmul_rn(in[sc[j]*FF + f], w);
        acc = __fadd_rn(acc, __fmul_rn(sv[j], xv));
    }
    outp[r*FF + f] = (PASS == 0) ? xla_tanh(acc) : acc;
}

// row L2 normalize: NEON-style fast-math vectorized reduce (verified).
__global__ void k_rownorm_vec() {
    int r = blockIdx.x * blockDim.x + threadIdx.x;
    if (r >= NN) return;
    float* row = &g_emb[r*FF];
    float a[16];
#pragma unroll
    for (int l = 0; l < 16; l++) a[l] = 0.f;
#pragma unroll 2
    for (int m = 0; m < 16; m++)
#pragma unroll
        for (int l = 0; l < 16; l++) {
            float v = row[m*16 + l];
            a[l] = __fmaf_rn(v, v, a[l]);
        }
    float c[4];
#pragma unroll
    for (int j = 0; j < 4; j++)
        c[j] = __fadd_rn(__fadd_rn(a[j], a[j+4]), __fadd_rn(a[j+8], a[j+12]));
    float d0 = __fadd_rn(c[0], c[2]);
    float d1 = __fadd_rn(c[1], c[3]);
    float s  = __fadd_rn(d0, d1);
    float nrm = fmaxf(__fsqrt_rn(s), 1e-12f);
#pragma unroll 8
    for (int f = 0; f < FF; f++) row[f] = __fdiv_rn(row[f], nrm);
}

// ---------------- fused sim GEMM + top-32, register-blocked ----------------
// 128x128 output tile per CTA, 256 threads, 8x8 micro-tile. Per output element
// the accumulation is a single sequential FMA chain over k (halves split at
// k=128, combined with one rounded add) — bit-identical to the passing R15
// kernel, just reorganized for register reuse (FFMA:LDS issue ratio 16:1).
__global__ __launch_bounds__(256) void k_simtopk3() {
    extern __shared__ float sm[];
    float* As   = sm;              // [8][128]
    float* Bs   = sm + 1024;       // [8][128]
    float* tile = sm + 2048;       // [128][129]
    float* lv   = tile + 128*129;  // [128][32]
    int*   li   = (int*)(lv + 128*KTOP);
    const int tid = threadIdx.x;
    const int rowBase = blockIdx.x << 7;
    const int tx = tid & 15, ty = tid >> 4;
    const int lr = tid & 127;
    const int lc4 = (tid >> 7) << 2;

    for (int i = tid; i < 128*KTOP; i += 256) { lv[i] = -3.4e38f; li[i] = 0; }
    __syncthreads();

    for (int ct = 0; ct < 128; ct++) {
        const int colBase = ct << 7;
#pragma unroll 1
        for (int half = 0; half < 2; half++) {
            float acc[8][8];
#pragma unroll
            for (int i = 0; i < 8; i++)
#pragma unroll
                for (int j = 0; j < 8; j++) acc[i][j] = 0.f;

#pragma unroll 1
            for (int kt = 0; kt < 16; kt++) {
                const int kk = half*128 + kt*8;
                float4 a4 = *(const float4*)&g_emb[(rowBase + lr)*FF + kk + lc4];
                float4 b4 = *(const float4*)&g_emb[(colBase + lr)*FF + kk + lc4];
                __syncthreads();
                As[(lc4+0)*128 + lr] = a4.x;
                As[(lc4+1)*128 + lr] = a4.y;
                As[(lc4+2)*128 + lr] = a4.z;
                As[(lc4+3)*128 + lr] = a4.w;
                Bs[(lc4+0)*128 + lr] = b4.x;
                Bs[(lc4+1)*128 + lr] = b4.y;
                Bs[(lc4+2)*128 + lr] = b4.z;
                Bs[(lc4+3)*128 + lr] = b4.w;
                __syncthreads();
#pragma unroll
                for (int k = 0; k < 8; k++) {
                    float a[8], b[8];
#pragma unroll
                    for (int i = 0; i < 8; i++) a[i] = As[k*128 + ty*8 + i];
#pragma unroll
                    for (int j = 0; j < 8; j++) b[j] = Bs[k*128 + tx*8 + j];
#pragma unroll
                    for (int i = 0; i < 8; i++)
#pragma unroll
                        for (int j = 0; j < 8; j++)
                            acc[i][j] = __fmaf_rn(a[i], b[j], acc[i][j]);
                }
            }
            if (half == 0) {
#pragma unroll
                for (int i = 0; i < 8; i++)
#pragma unroll
                    for (int j = 0; j < 8; j++)
                        tile[(ty*8 + i)*129 + tx*8 + j] = acc[i][j];
            } else {
#pragma unroll
                for (int i = 0; i < 8; i++)
#pragma unroll
                    for (int j = 0; j < 8; j++) {
                        float* tp = &tile[(ty*8 + i)*129 + tx*8 + j];
                        *tp = __fadd_rn(*tp, acc[i][j]);
                    }
            }
        }
        __syncthreads();

        if (tid < 128) {
            float* L  = lv + tid*KTOP;
            int*   LI = li + tid*KTOP;
            float vm = L[KTOP-1];
#pragma unroll 1
            for (int cc = 0; cc < 128; cc++) {
                float v = tile[tid*129 + cc];
                if (v > vm) {
                    int k = KTOP-1;
                    while (k > 0 && L[k-1] < v) {
                        L[k] = L[k-1];
                        LI[k] = LI[k-1];
                        --k;
                    }
                    L[k] = v;
                    LI[k] = colBase + cc;
                    vm = L[KTOP-1];
                }
            }
        }
        __syncthreads();
    }

    for (int i = tid; i < 128*KTOP; i += 256) {
        int r = i >> 5, k = i & 31;
        g_topv[(rowBase + r)*KTOP + k] = lv[r*KTOP + k];
        g_topi[(rowBase + r)*KTOP + k] = li[r*KTOP + k];
    }
}

// ---------------- output writers ----------------
__global__ void k_write_fixed(const void* __restrict__ idx, const float* __restrict__ vals,
                              float* __restrict__ out, long long osz) {
    int e = blockIdx.x * blockDim.x + threadIdx.x;
    if (e >= EE) return;
    OSTORE(OFF_NEWIDX + e,        (float)row_raw(idx, e));
    OSTORE(OFF_NEWIDX + ETOT + e, (float)col_raw(idx, e));
    OSTORE(OFF_NEWV + e,          vals[e]);
}

__global__ void k_write_topk(float* __restrict__ out, long long osz) {
    int i = blockIdx.x * blockDim.x + threadIdx.x;
    if (i >= NK) return;
    int row = i >> 5;
    float fr = (float)row;
    float fc = (float)g_topi[i];
    float v  = g_topv[i];
    OSTORE(OFF_MIDIDX + i,          fr);
    OSTORE(OFF_MIDIDX + NK + i,     fc);
    OSTORE(OFF_MIDIDX + 2*NK + i,   fc);
    OSTORE(OFF_MIDIDX + 3*NK + i,   fr);
    OSTORE(OFF_MIDV + i,            v);
    OSTORE(OFF_MIDV + NK + i,       v);
    OSTORE(OFF_NEWIDX + EE + i,             fr);
    OSTORE(OFF_NEWIDX + EE + NK + i,        fc);
    OSTORE(OFF_NEWIDX + ETOT + EE + i,      fc);
    OSTORE(OFF_NEWIDX + ETOT + EE + NK + i, fr);
    OSTORE(OFF_NEWV + EE + i,       v);
    OSTORE(OFF_NEWV + EE + NK + i,  v);
}

// ---------------- new graph: degrees + CSR ----------------
__global__ void k_zero() {
    int r = blockIdx.x * blockDim.x + threadIdx.x;
    if (r >= NN) return;
    g_hist[r] = 0;
    g_degsum[r] = 0.f;
}

__global__ void k_hist(const float* __restrict__ vals) {
    int e = blockIdx.x * blockDim.x + threadIdx.x;
    if (e >= ETOT) return;
    int row; float val;
    if (e < EE)           { row = e >> 4;                         val = vals[e]; }
    else if (e < EE + NK) { int i = e - EE;      row = i >> 5;    val = g_topv[i]; }
    else                  { int i = e - EE - NK; row = g_topi[i]; val = g_topv[i]; }
    atomicAdd(&g_hist[row], 1);
    atomicAdd(&g_degsum[row], val);
}

__global__ void k_isnew() {
    int r = blockIdx.x * blockDim.x + threadIdx.x;
    if (r >= NN) return;
    float t = __fadd_rn(__fsqrt_rn(g_degsum[r]), 1e-10f);
    g_isnew[r] = __fdiv_rn(1.f, t);
}

__global__ void k_rowptr() {
    __shared__ int tsum[256];
    __shared__ int tpre[256];
    int t = threadIdx.x;
    int s = 0;
    for (int j = 0; j < 64; j++) s += g_hist[t*64 + j];
    tsum[t] = s;
    __syncthreads();
    if (t == 0) {
        int run = 0;
        for (int i = 0; i < 256; i++) { tpre[i] = run; run += tsum[i]; }
    }
    __syncthreads();
    int run = tpre[t];
    for (int j = 0; j < 64; j++) {
        int r = t*64 + j;
        g_rowptr[r] = run;
        g_cursor[r] = run;
        run += g_hist[r];
    }
    if (t == 255) g_rowptr[NN] = run;
}

__global__ void k_scatter(const void* __restrict__ idx, const float* __restrict__ vals) {
    int e = blockIdx.x * blockDim.x + threadIdx.x;
    if (e >= ETOT) return;
    int row, col; float val;
    if (e < EE) {
        row = e >> 4;
        col = col_of(idx, e);
        val = vals[e];
    } else if (e < EE + NK) {
        int i = e - EE;
        row = i >> 5;
        col = g_topi[i];
        val = g_topv[i];
    } else {
        int i = e - EE - NK;
        row = g_topi[i];
        col = i >> 5;
        val = g_topv[i];
    }
    int p = atomicAdd(&g_cursor[row], 1);
    g_csr_col[p] = col;
    g_csr_val[p] = __fmul_rn(__fmul_rn(val, g_isnew[row]), g_isnew[col]);
}

// ---------------- dense GEMM; scratch operands resolved in device code ----------------
template<int WHICH>
__global__ __launch_bounds__(256) void k_dgemm(const float* __restrict__ Aarg,
                                               const float* __restrict__ B) {
    constexpr int Ka = WHICH ? HH : FF;
    constexpr int Nc = WHICH ? CC : HH;
    const float* A = WHICH ? g_h : Aarg;
    float* C       = WHICH ? g_hw2 : g_xw1;
    __shared__ float As[16][64];
    __shared__ float Bs[16][64];
    int tid = threadIdx.x;
    int rb = blockIdx.x * 64, cb = blockIdx.y * 64;
    int tx = tid & 15, ty = tid >> 4;
    float acc[4][4];
#pragma unroll
    for (int i = 0; i < 4; i++)
#pragma unroll
        for (int j = 0; j < 4; j++) acc[i][j] = 0.f;

    int ar = tid >> 2, ac4 = (tid & 3) * 4;
    int bk = tid >> 4, bc = (tid & 15) * 4;
    for (int kk = 0; kk < Ka; kk += 16) {
        float4 a4 = *(const float4*)&A[(rb + ar)*Ka + kk + ac4];
        float4 b4;
        int bcg = cb + bc;
        if (bcg + 3 < Nc) {
            b4 = *(const float4*)&B[(kk + bk)*Nc + bcg];
        } else {
            b4.x = (bcg + 0 < Nc) ? B[(kk + bk)*Nc + bcg + 0] : 0.f;
            b4.y = (bcg + 1 < Nc) ? B[(kk + bk)*Nc + bcg + 1] : 0.f;
            b4.z = (bcg + 2 < Nc) ? B[(kk + bk)*Nc + bcg + 2] : 0.f;
            b4.w = (bcg + 3 < Nc) ? B[(kk + bk)*Nc + bcg + 3] : 0.f;
        }
        __syncthreads();
        As[ac4+0][ar] = a4.x; As[ac4+1][ar] = a4.y; As[ac4+2][ar] = a4.z; As[ac4+3][ar] = a4.w;
        Bs[bk][bc+0] = b4.x; Bs[bk][bc+1] = b4.y; Bs[bk][bc+2] = b4.z; Bs[bk][bc+3] = b4.w;
        __syncthreads();
#pragma unroll
        for (int k = 0; k < 16; k++) {
            float a[4], b[4];
#pragma unroll
            for (int i = 0; i < 4; i++) a[i] = As[k][ty*4 + i];
#pragma unroll
            for (int j = 0; j < 4; j++) b[j] = Bs[k][tx*4 + j];
#pragma unroll
            for (int i = 0; i < 4; i++)
#pragma unroll
                for (int j = 0; j < 4; j++) acc[i][j] += a[i] * b[j];
        }
    }
#pragma unroll
    for (int i = 0; i < 4; i++)
#pragma unroll
        for (int j = 0; j < 4; j++) {
            int cc = cb + tx*4 + j;
            if (cc < Nc) C[(rb + ty*4 + i)*Nc + cc] = acc[i][j];
        }
}

// CSR gather SpMM layer 1: g_h = relu(spmm(new, g_xw1) + bg1)
__global__ void k_spmm_csr_h(const float* __restrict__ bias) {
    int r = blockIdx.x;
    int f = threadIdx.x;
    int p0 = g_rowptr[r], p1 = g_rowptr[r+1];
    float acc = 0.f;
    for (int p = p0; p < p1; p++) acc += g_csr_val[p] * g_xw1[g_csr_col[p]*HH + f];
    acc += bias[f];
    g_h[r*HH + f] = fmaxf(acc, 0.f);
}

// CSR gather SpMM layer 2 (logits): out = spmm(new, g_hw2) + bg2
__global__ void k_spmm_csr_out(const float* __restrict__ bias,
                               float* __restrict__ out, long long osz) {
    int r = blockIdx.x;
    int f = threadIdx.x;
    int p0 = g_rowptr[r], p1 = g_rowptr[r+1];
    float acc = 0.f;
    for (int p = p0; p < p1; p++) acc += g_csr_val[p] * g_hw2[g_csr_col[p]*CC + f];
    acc += bias[f];
    OSTORE((long long)r*CC + f, acc);
}

// ---------------- launch ----------------
extern "C" void kernel_launch(void* const* d_in, const int* in_sizes, int n_in,
                              void* d_out, int out_size) {
    const float* x       = (const float*)d_in[0];
    const void*  adj_idx = d_in[1];
    const float* adj_val = (const float*)d_in[2];
    const float* Wd1     = (const float*)d_in[3];
    const float* Wd2     = (const float*)d_in[4];
    const float* Wg1     = (const float*)d_in[5];
    const float* bg1     = (const float*)d_in[6];
    const float* Wg2     = (const float*)d_in[7];
    const float* bg2     = (const float*)d_in[8];
    float* out = (float*)d_out;
    const long long osz = (long long)out_size;

    k_detect8<<<1, 256>>>(adj_idx);

    k_deg0<<<NN/256, 256>>>(adj_val);
    k_nvals0<<<EE/256, 256>>>(adj_idx, adj_val);
    k_spmm16<0><<<NN, FF>>>(x, Wd1, adj_idx);
    k_spmm16<1><<<NN, FF>>>(x, Wd2, adj_idx);
    k_rownorm_vec<<<NN/256, 256>>>();

    const int SIM_SMEM = (2048 + 128*129 + 2*128*KTOP) * 4;  // 107008 bytes
    cudaFuncSetAttribute(k_simtopk3, cudaFuncAttributeMaxDynamicSharedMemorySize, SIM_SMEM);
    k_simtopk3<<<NN/128, 256, SIM_SMEM>>>();

    k_write_fixed<<<EE/256, 256>>>(adj_idx, adj_val, out, osz);
    k_write_topk<<<NK/256, 256>>>(out, osz);

    k_zero<<<NN/256, 256>>>();
    k_hist<<<ETOT/256, 256>>>(adj_val);
    k_isnew<<<NN/256, 256>>>();
    k_rowptr<<<1, 256>>>();
    k_scatter<<<ETOT/256, 256>>>(adj_idx, adj_val);

    // task GCN (commuted dense layers: spmm(A,x)@W == spmm(A, x@W))
    k_dgemm<0><<<dim3(NN/64, HH/64), 256>>>(x, Wg1);
    k_spmm_csr_h<<<NN, HH>>>(bg1);
    k_dgemm<1><<<dim3(NN/64, 1), 256>>>(x, Wg2);
    k_spmm_csr_out<<<NN, CC>>>(bg2, out, osz);
}